// round 1
// baseline (speedup 1.0000x reference)
#include <cuda_runtime.h>

#define Bb 16
#define Qq 64
#define KK 512
#define Dd 512
#define Hh 256
#define QT 4
#define KT 32

// Scratch (device globals; no allocations allowed)
__device__ float g_qh[Bb * Qq * Hh];      // 1 MB
__device__ float g_kh[Bb * KK * Hh];      // 8 MB
__device__ float g_attn[Bb * Qq * KK];    // 2 MB

__device__ __forceinline__ float tanh_safe(float x) {
    // tanh via exp(-2|x|): ~1e-6 accuracy, 2 MUFU ops, no overflow/NaN for any x
    float ax = fabsf(x);
    float e  = __expf(-2.0f * ax);
    float t  = __fdividef(1.0f - e, 1.0f + e);
    return copysignf(t, x);
}

// C[M,N] = A[M,K] @ B[K,N], row-major. 64x64 tile, 256 threads, 4x4 per thread.
// Requires M%64==0, N%64==0, K%16==0. blockIdx.z batches via strides.
__global__ void sgemm64(const float* __restrict__ A, const float* __restrict__ Bm,
                        float* __restrict__ C, int M, int K, int N,
                        long sA, long sB, long sC) {
    A  += (long)blockIdx.z * sA;
    Bm += (long)blockIdx.z * sB;
    C  += (long)blockIdx.z * sC;
    const int bm = blockIdx.y * 64, bn = blockIdx.x * 64;

    __shared__ float As[16][64];   // transposed A tile: As[k][m]
    __shared__ float Bs[16][64];   // Bs[k][n]

    const int tid  = threadIdx.x;
    const int tx   = tid & 15, ty = tid >> 4;          // 16x16 thread grid
    const int aRow = tid >> 2, aCol = (tid & 3) << 2;  // A tile load: 64 rows x 16 cols
    const int bRow = tid >> 4, bCol = (tid & 15) << 2; // B tile load: 16 rows x 64 cols

    float acc[4][4] = {};

    for (int k0 = 0; k0 < K; k0 += 16) {
        float4 av = *(const float4*)(A  + (long)(bm + aRow) * K + k0 + aCol);
        float4 bv = *(const float4*)(Bm + (long)(k0 + bRow) * N + bn + bCol);
        __syncthreads();
        As[aCol + 0][aRow] = av.x;
        As[aCol + 1][aRow] = av.y;
        As[aCol + 2][aRow] = av.z;
        As[aCol + 3][aRow] = av.w;
        *(float4*)&Bs[bRow][bCol] = bv;
        __syncthreads();
        #pragma unroll
        for (int kk = 0; kk < 16; kk++) {
            float4 aq = *(const float4*)&As[kk][ty * 4];
            float4 bq = *(const float4*)&Bs[kk][tx * 4];
            float a4[4] = {aq.x, aq.y, aq.z, aq.w};
            float b4[4] = {bq.x, bq.y, bq.z, bq.w};
            #pragma unroll
            for (int i = 0; i < 4; i++)
                #pragma unroll
                for (int j = 0; j < 4; j++)
                    acc[i][j] = fmaf(a4[i], b4[j], acc[i][j]);
        }
    }
    #pragma unroll
    for (int i = 0; i < 4; i++) {
        float4 o = make_float4(acc[i][0], acc[i][1], acc[i][2], acc[i][3]);
        *(float4*)(C + (long)(bm + ty * 4 + i) * N + bn + tx * 4) = o;
    }
}

// Fused additive-attention scoring + masked softmax.
// Block = (batch b, 4 consecutive q rows). 256 threads = 8 warps.
// scores[q][k] = sum_h Wv[h] * tanh(qh[b,q,h] + kh[b,k,h]); softmax over k with mask.
__global__ void score_softmax(const float* __restrict__ Wv, const int* __restrict__ vlens) {
    const int bq   = blockIdx.x;        // 0 .. B*(Q/QT)-1
    const int b    = bq >> 4;           // / (Q/QT = 16)
    const int q0   = (bq & 15) * QT;
    const int tid  = threadIdx.x;
    const int lane = tid & 31;
    const int w    = tid >> 5;

    __shared__ float sq[QT][Hh];        // 4 KB
    __shared__ float sk[KT][Hh];        // 32 KB
    __shared__ float ssc[QT][KK];       // 8 KB

    // Stage the 4 q-rows (1024 floats = 256 float4)
    {
        const float4* src = (const float4*)(g_qh + (long)(b * Qq + q0) * Hh);
        ((float4*)&sq[0][0])[tid] = src[tid];
    }
    // Per-lane Wv slice (h = lane + 32*i)
    float wv[8];
    #pragma unroll
    for (int i = 0; i < 8; i++) wv[i] = Wv[lane + 32 * i];
    __syncthreads();

    // Per-lane q slices for all 4 rows
    float qreg[QT][8];
    #pragma unroll
    for (int q = 0; q < QT; q++)
        #pragma unroll
        for (int i = 0; i < 8; i++) qreg[q][i] = sq[q][lane + 32 * i];

    const float* kbase = g_kh + (long)b * KK * Hh;

    for (int kt = 0; kt < KK / KT; kt++) {
        __syncthreads();  // protect previous tile reads
        // Load kh tile: 32 rows x 256 h = 2048 float4, 8 per thread (coalesced)
        const float4* gsrc = (const float4*)(kbase + (long)kt * KT * Hh);
        #pragma unroll
        for (int i = 0; i < 8; i++)
            ((float4*)&sk[0][0])[tid + 256 * i] = gsrc[tid + 256 * i];
        __syncthreads();

        // 4 q x 32 k = 128 (q,k) pairs; warp w handles pairs [w*16, w*16+16)
        #pragma unroll 2
        for (int pp = 0; pp < 16; pp++) {
            int p = w * 16 + pp;
            int q = p >> 5;
            int k = p & 31;
            float s = 0.f;
            #pragma unroll
            for (int i = 0; i < 8; i++) {
                float x = qreg[q][i] + sk[k][lane + 32 * i];  // conflict-free LDS
                s = fmaf(wv[i], tanh_safe(x), s);
            }
            #pragma unroll
            for (int off = 16; off; off >>= 1)
                s += __shfl_xor_sync(0xffffffffu, s, off);
            if (lane == 0) ssc[q][kt * KT + k] = s;
        }
    }
    __syncthreads();

    // Masked softmax: warp w (w < 4) owns q-row (q0 + w), 512 scores, 16 per lane
    if (w < QT) {
        const int vl = vlens[b];
        float vals[16];
        float mx = -3.0e38f;
        #pragma unroll
        for (int i = 0; i < 16; i++) {
            int kk2 = lane + 32 * i;
            float v = ssc[w][kk2];
            if (kk2 >= vl) v = -1e6f;
            vals[i] = v;
            mx = fmaxf(mx, v);
        }
        #pragma unroll
        for (int off = 16; off; off >>= 1)
            mx = fmaxf(mx, __shfl_xor_sync(0xffffffffu, mx, off));
        float sum = 0.f;
        #pragma unroll
        for (int i = 0; i < 16; i++) {
            float e = __expf(vals[i] - mx);   // masked -> underflows to exactly 0
            vals[i] = e;
            sum += e;
        }
        #pragma unroll
        for (int off = 16; off; off >>= 1)
            sum += __shfl_xor_sync(0xffffffffu, sum, off);
        float inv = __fdividef(1.f, sum);
        float* dst = g_attn + (long)(b * Qq + q0 + w) * KK;
        #pragma unroll
        for (int i = 0; i < 16; i++)
            dst[lane + 32 * i] = vals[i] * inv;
    }
}

extern "C" void kernel_launch(void* const* d_in, const int* in_sizes, int n_in,
                              void* d_out, int out_size) {
    const float* queries = (const float*)d_in[0];  // [16,64,512]
    const float* keys    = (const float*)d_in[1];  // [16,512,512]
    const float* values  = (const float*)d_in[2];  // [16,512,512]
    const int*   vlens   = (const int*)d_in[3];    // [16]
    const float* Wq      = (const float*)d_in[4];  // [512,256]
    const float* Wk      = (const float*)d_in[5];  // [512,256]
    const float* Wv      = (const float*)d_in[6];  // [256]
    float* out = (float*)d_out;                    // [16,64,512]

    static float* qh = nullptr;
    static float* kh = nullptr;
    static float* attn = nullptr;
    if (!qh) {
        cudaGetSymbolAddress((void**)&qh, g_qh);
        cudaGetSymbolAddress((void**)&kh, g_kh);
        cudaGetSymbolAddress((void**)&attn, g_attn);
    }

    // q-proj: [1024,512] @ [512,256]
    sgemm64<<<dim3(Hh / 64, (Bb * Qq) / 64, 1), 256>>>(
        queries, Wq, qh, Bb * Qq, Dd, Hh, 0, 0, 0);
    // k-proj: [8192,512] @ [512,256]
    sgemm64<<<dim3(Hh / 64, (Bb * KK) / 64, 1), 256>>>(
        keys, Wk, kh, Bb * KK, Dd, Hh, 0, 0, 0);
    // scores + masked softmax
    score_softmax<<<Bb * (Qq / QT), 256>>>(Wv, vlens);
    // out = attn @ values, batched over 16
    sgemm64<<<dim3(Dd / 64, Qq / 64, Bb), 256>>>(
        attn, values, out, Qq, KK, Dd,
        (long)Qq * KK, (long)KK * Dd, (long)Qq * Dd);
}

// round 2
// speedup vs baseline: 1.6199x; 1.6199x over previous
#include <cuda_runtime.h>

#define Bb 16
#define Qq 64
#define KK 512
#define Dd 512
#define Hh 256
#define QT 4
#define KT 32

// Scratch (device globals; no allocations allowed)
__device__ float g_qh[Bb * Qq * Hh];      // 1 MB
__device__ float g_kh[Bb * KK * Hh];      // 8 MB
__device__ float g_attn[Bb * Qq * KK];    // 2 MB

__device__ __forceinline__ float tanhx(float x) {
    float y;
    asm("tanh.approx.f32 %0, %1;" : "=f"(y) : "f"(x));
    return y;
}

// Fused q-proj + k-proj. Row-space: rows [0,1024) = queries@Wq -> g_qh,
// rows [1024, 9216) = keys@Wk -> g_kh. Key tiles fully past valid_len skipped.
// grid = (Hh/64 = 4, 144), block = 256.
__global__ void proj_gemm(const float* __restrict__ queries,
                          const float* __restrict__ keys,
                          const float* __restrict__ Wq,
                          const float* __restrict__ Wk,
                          const int* __restrict__ vlens) {
    const int row0 = blockIdx.y * 64;
    const int bn   = blockIdx.x * 64;

    const float* A;
    const float* Bm;
    float* C;
    if (row0 < Bb * Qq) {
        A  = queries + (long)row0 * Dd;
        Bm = Wq;
        C  = g_qh + (long)row0 * Hh;
    } else {
        const int krow = row0 - Bb * Qq;
        const int b    = krow >> 9;           // / KK
        if ((krow & (KK - 1)) >= vlens[b]) return;  // masked-out tile: never read
        A  = keys + (long)krow * Dd;
        Bm = Wk;
        C  = g_kh + (long)krow * Hh;
    }

    __shared__ float As[16][64];
    __shared__ float Bs[16][64];

    const int tid  = threadIdx.x;
    const int tx   = tid & 15, ty = tid >> 4;
    const int aRow = tid >> 2, aCol = (tid & 3) << 2;
    const int bRow = tid >> 4, bCol = (tid & 15) << 2;

    float acc[4][4] = {};

    for (int k0 = 0; k0 < Dd; k0 += 16) {
        float4 av = *(const float4*)(A  + (long)aRow * Dd + k0 + aCol);
        float4 bv = *(const float4*)(Bm + (long)(k0 + bRow) * Hh + bn + bCol);
        __syncthreads();
        As[aCol + 0][aRow] = av.x;
        As[aCol + 1][aRow] = av.y;
        As[aCol + 2][aRow] = av.z;
        As[aCol + 3][aRow] = av.w;
        *(float4*)&Bs[bRow][bCol] = bv;
        __syncthreads();
        #pragma unroll
        for (int kk = 0; kk < 16; kk++) {
            float4 aq = *(const float4*)&As[kk][ty * 4];
            float4 bq = *(const float4*)&Bs[kk][tx * 4];
            float a4[4] = {aq.x, aq.y, aq.z, aq.w};
            float b4[4] = {bq.x, bq.y, bq.z, bq.w};
            #pragma unroll
            for (int i = 0; i < 4; i++)
                #pragma unroll
                for (int j = 0; j < 4; j++)
                    acc[i][j] = fmaf(a4[i], b4[j], acc[i][j]);
        }
    }
    #pragma unroll
    for (int i = 0; i < 4; i++) {
        float4 o = make_float4(acc[i][0], acc[i][1], acc[i][2], acc[i][3]);
        *(float4*)(C + (long)(ty * 4 + i) * Hh + bn + tx * 4) = o;
    }
}

// Fused additive-attention scoring + masked softmax.
// Block = (batch b, 4 consecutive q rows). 256 threads = 8 warps.
__global__ void score_softmax(const float* __restrict__ Wv, const int* __restrict__ vlens) {
    const int bq   = blockIdx.x;
    const int b    = bq >> 4;
    const int q0   = (bq & 15) * QT;
    const int tid  = threadIdx.x;
    const int lane = tid & 31;
    const int w    = tid >> 5;
    const int vl   = vlens[b];

    __shared__ float sq[QT][Hh];        // 4 KB
    __shared__ float sk[KT][Hh];        // 32 KB
    __shared__ float ssc[QT][KK];       // 8 KB

    {
        const float4* src = (const float4*)(g_qh + (long)(b * Qq + q0) * Hh);
        ((float4*)&sq[0][0])[tid] = src[tid];
    }
    float wv[8];
    #pragma unroll
    for (int i = 0; i < 8; i++) wv[i] = Wv[lane + 32 * i];
    __syncthreads();

    float qreg[QT][8];
    #pragma unroll
    for (int q = 0; q < QT; q++)
        #pragma unroll
        for (int i = 0; i < 8; i++) qreg[q][i] = sq[q][lane + 32 * i];

    const float* kbase = g_kh + (long)b * KK * Hh;
    const int ktmax = (vl + KT - 1) / KT;   // tiles fully past vl are masked anyway

    for (int kt = 0; kt < ktmax; kt++) {
        __syncthreads();
        const float4* gsrc = (const float4*)(kbase + (long)kt * KT * Hh);
        #pragma unroll
        for (int i = 0; i < 8; i++)
            ((float4*)&sk[0][0])[tid + 256 * i] = gsrc[tid + 256 * i];
        __syncthreads();

        #pragma unroll 2
        for (int pp = 0; pp < 16; pp++) {
            int p = w * 16 + pp;
            int q = p >> 5;
            int k = p & 31;
            float s = 0.f;
            #pragma unroll
            for (int i = 0; i < 8; i++) {
                float x = qreg[q][i] + sk[k][lane + 32 * i];
                s = fmaf(wv[i], tanhx(x), s);
            }
            #pragma unroll
            for (int off = 16; off; off >>= 1)
                s += __shfl_xor_sync(0xffffffffu, s, off);
            if (lane == 0) ssc[q][kt * KT + k] = s;
        }
    }
    __syncthreads();

    // Masked softmax: warp w (w < 4) owns q-row (q0 + w)
    if (w < QT) {
        float vals[16];
        float mx = -3.0e38f;
        #pragma unroll
        for (int i = 0; i < 16; i++) {
            int kk2 = lane + 32 * i;
            float v = (kk2 < vl) ? ssc[w][kk2] : -1e6f;  // garbage beyond vl masked
            vals[i] = v;
            mx = fmaxf(mx, v);
        }
        #pragma unroll
        for (int off = 16; off; off >>= 1)
            mx = fmaxf(mx, __shfl_xor_sync(0xffffffffu, mx, off));
        float sum = 0.f;
        #pragma unroll
        for (int i = 0; i < 16; i++) {
            float e = __expf(vals[i] - mx);   // masked -> exactly 0
            vals[i] = e;
            sum += e;
        }
        #pragma unroll
        for (int off = 16; off; off >>= 1)
            sum += __shfl_xor_sync(0xffffffffu, sum, off);
        float inv = __fdividef(1.f, sum);
        float* dst = g_attn + (long)(b * Qq + q0 + w) * KK;
        #pragma unroll
        for (int i = 0; i < 16; i++)
            dst[lane + 32 * i] = vals[i] * inv;
    }
}

// out[b] = attn[b] (64x512) @ values[b] (512x512). K-loop bounded by valid_len
// (attn is exactly 0 for k >= vl). grid = (Dd/64 = 8, 1, Bb), block = 256.
__global__ void av_gemm(const float* __restrict__ values, float* __restrict__ out,
                        const int* __restrict__ vlens) {
    const int b  = blockIdx.z;
    const int bn = blockIdx.x * 64;
    const float* A  = g_attn + (long)b * Qq * KK;
    const float* Bm = values + (long)b * KK * Dd;
    float* C        = out + (long)b * Qq * Dd;
    const int kmax  = (vlens[b] + 15) & ~15;   // <= 512 since vl <= 512

    __shared__ float As[16][64];
    __shared__ float Bs[16][64];

    const int tid  = threadIdx.x;
    const int tx   = tid & 15, ty = tid >> 4;
    const int aRow = tid >> 2, aCol = (tid & 3) << 2;
    const int bRow = tid >> 4, bCol = (tid & 15) << 2;

    float acc[4][4] = {};

    for (int k0 = 0; k0 < kmax; k0 += 16) {
        float4 av = *(const float4*)(A  + (long)aRow * KK + k0 + aCol);
        float4 bv = *(const float4*)(Bm + (long)(k0 + bRow) * Dd + bn + bCol);
        __syncthreads();
        As[aCol + 0][aRow] = av.x;
        As[aCol + 1][aRow] = av.y;
        As[aCol + 2][aRow] = av.z;
        As[aCol + 3][aRow] = av.w;
        *(float4*)&Bs[bRow][bCol] = bv;
        __syncthreads();
        #pragma unroll
        for (int kk = 0; kk < 16; kk++) {
            float4 aq = *(const float4*)&As[kk][ty * 4];
            float4 bq = *(const float4*)&Bs[kk][tx * 4];
            float a4[4] = {aq.x, aq.y, aq.z, aq.w};
            float b4[4] = {bq.x, bq.y, bq.z, bq.w};
            #pragma unroll
            for (int i = 0; i < 4; i++)
                #pragma unroll
                for (int j = 0; j < 4; j++)
                    acc[i][j] = fmaf(a4[i], b4[j], acc[i][j]);
        }
    }
    #pragma unroll
    for (int i = 0; i < 4; i++) {
        float4 o = make_float4(acc[i][0], acc[i][1], acc[i][2], acc[i][3]);
        *(float4*)(C + (long)(ty * 4 + i) * Dd + bn + tx * 4) = o;
    }
}

extern "C" void kernel_launch(void* const* d_in, const int* in_sizes, int n_in,
                              void* d_out, int out_size) {
    const float* queries = (const float*)d_in[0];  // [16,64,512]
    const float* keys    = (const float*)d_in[1];  // [16,512,512]
    const float* values  = (const float*)d_in[2];  // [16,512,512]
    const int*   vlens   = (const int*)d_in[3];    // [16]
    const float* Wq      = (const float*)d_in[4];  // [512,256]
    const float* Wk      = (const float*)d_in[5];  // [512,256]
    const float* Wv      = (const float*)d_in[6];  // [256]
    float* out = (float*)d_out;                    // [16,64,512]

    // q-proj + k-proj fused into one full-chip launch
    proj_gemm<<<dim3(Hh / 64, (Bb * Qq + Bb * KK) / 64), 256>>>(
        queries, keys, Wq, Wk, vlens);
    // scores + masked softmax (valid_len-bounded)
    score_softmax<<<Bb * (Qq / QT), 256>>>(Wv, vlens);
    // out = attn @ values, batched, K bounded by valid_len
    av_gemm<<<dim3(Dd / 64, 1, Bb), 256>>>(values, out, vlens);
}

// round 3
// speedup vs baseline: 2.0863x; 1.2879x over previous
#include <cuda_runtime.h>

#define Bb 16
#define Qq 64
#define KK 512
#define Dd 512
#define Hh 256

// Scratch (device globals; no allocations allowed)
__device__ float g_qh[Bb * Qq * Hh];      // 1 MB
__device__ float g_kh[Bb * KK * Hh];      // 8 MB
__device__ float g_attn[Bb * Qq * KK];    // 2 MB

__device__ __forceinline__ float tanhx(float x) {
    float y;
    asm("tanh.approx.f32 %0, %1;" : "=f"(y) : "f"(x));
    return y;
}

// ---------------------------------------------------------------------------
// Fused q-proj + k-proj GEMM. Row-space: [0,1024) = queries@Wq -> g_qh,
// [1024,9216) = keys@Wk -> g_kh (tiles fully past valid_len skipped).
// 128x64 tile, 256 threads, 8x4 microtile, double-buffered smem, 1 sync/slice.
// grid = (Hh/64 = 4, 72), block = 256.
// ---------------------------------------------------------------------------
__global__ __launch_bounds__(256) void proj_gemm(
        const float* __restrict__ queries, const float* __restrict__ keys,
        const float* __restrict__ Wq, const float* __restrict__ Wk,
        const int* __restrict__ vlens) {
    const int row0 = blockIdx.y * 128;
    const int bn   = blockIdx.x * 64;

    const float *A, *Bm;
    float* C;
    if (row0 < Bb * Qq) {
        A = queries + (long)row0 * Dd; Bm = Wq; C = g_qh + (long)row0 * Hh;
    } else {
        const int krow = row0 - Bb * Qq;
        const int b    = krow >> 9;
        if ((krow & (KK - 1)) >= vlens[b]) return;   // fully-masked tile
        A = keys + (long)krow * Dd; Bm = Wk; C = g_kh + (long)krow * Hh;
    }

    __shared__ float As[2][16][128];   // transposed: As[k][m]
    __shared__ float Bs[2][16][64];

    const int tid = threadIdx.x;
    const int tx  = tid & 15, ty = tid >> 4;          // micro: rows ty*8..+7, cols tx*4..+3
    const int ar0 = tid >> 2, akc = (tid & 3) << 2;   // A load: 2 float4/thread
    const int br  = tid >> 4, bc  = (tid & 15) << 2;  // B load: 1 float4/thread

    float4 ra0, ra1, rb;
    // prologue: slice 0
    ra0 = *(const float4*)(A + (long)ar0 * Dd + akc);
    ra1 = *(const float4*)(A + (long)(ar0 + 64) * Dd + akc);
    rb  = *(const float4*)(Bm + (long)br * Hh + bn + bc);
    As[0][akc + 0][ar0] = ra0.x; As[0][akc + 1][ar0] = ra0.y;
    As[0][akc + 2][ar0] = ra0.z; As[0][akc + 3][ar0] = ra0.w;
    As[0][akc + 0][ar0 + 64] = ra1.x; As[0][akc + 1][ar0 + 64] = ra1.y;
    As[0][akc + 2][ar0 + 64] = ra1.z; As[0][akc + 3][ar0 + 64] = ra1.w;
    *(float4*)&Bs[0][br][bc] = rb;
    __syncthreads();

    float acc[8][4] = {};

    for (int s = 0; s < Dd / 16; s++) {
        const int cur = s & 1;
        if (s + 1 < Dd / 16) {
            const int k0 = (s + 1) * 16;
            ra0 = *(const float4*)(A + (long)ar0 * Dd + k0 + akc);
            ra1 = *(const float4*)(A + (long)(ar0 + 64) * Dd + k0 + akc);
            rb  = *(const float4*)(Bm + (long)(k0 + br) * Hh + bn + bc);
        }
        #pragma unroll
        for (int kk = 0; kk < 16; kk++) {
            float4 x0 = *(const float4*)&As[cur][kk][ty * 8];
            float4 x1 = *(const float4*)&As[cur][kk][ty * 8 + 4];
            float4 y  = *(const float4*)&Bs[cur][kk][tx * 4];
            float a8[8] = {x0.x, x0.y, x0.z, x0.w, x1.x, x1.y, x1.z, x1.w};
            float b4[4] = {y.x, y.y, y.z, y.w};
            #pragma unroll
            for (int i = 0; i < 8; i++)
                #pragma unroll
                for (int j = 0; j < 4; j++)
                    acc[i][j] = fmaf(a8[i], b4[j], acc[i][j]);
        }
        if (s + 1 < Dd / 16) {
            const int nb = (s + 1) & 1;
            As[nb][akc + 0][ar0] = ra0.x; As[nb][akc + 1][ar0] = ra0.y;
            As[nb][akc + 2][ar0] = ra0.z; As[nb][akc + 3][ar0] = ra0.w;
            As[nb][akc + 0][ar0 + 64] = ra1.x; As[nb][akc + 1][ar0 + 64] = ra1.y;
            As[nb][akc + 2][ar0 + 64] = ra1.z; As[nb][akc + 3][ar0 + 64] = ra1.w;
            *(float4*)&Bs[nb][br][bc] = rb;
        }
        __syncthreads();
    }
    #pragma unroll
    for (int i = 0; i < 8; i++) {
        float4 o = make_float4(acc[i][0], acc[i][1], acc[i][2], acc[i][3]);
        *(float4*)(C + (long)(ty * 8 + i) * Hh + bn + tx * 4) = o;
    }
}

// ---------------------------------------------------------------------------
// Fused scoring + masked softmax, shuffle-free scoring.
// Block = 128 threads = 4 warps; warp w owns q-row (q0+w); lane = k within tile.
// sk padded to 257 floats/row -> sk[lane][h] conflict-free.
// swq packs (qh, Wv) so one broadcast LDS.64 feeds both operands.
// Scores stay in per-lane registers vals[16] (k = 32*t + lane); softmax fused.
// grid = Bb*(Qq/4) = 256, block = 128.
// ---------------------------------------------------------------------------
__global__ __launch_bounds__(128) void score_softmax(
        const float* __restrict__ Wv, const int* __restrict__ vlens) {
    const int bq   = blockIdx.x;
    const int b    = bq >> 4;
    const int q0   = (bq & 15) * 4;
    const int tid  = threadIdx.x;
    const int lane = tid & 31;
    const int w    = tid >> 5;
    const int vl   = vlens[b];

    __shared__ float  sk[32][257];      // ~32.1 KB, padded
    __shared__ float2 swq[4][256];      // 8 KB  (qh, Wv) pairs

    // fill swq: 1024 float2, 8 per thread
    {
        const float* qbase = g_qh + (long)(b * Qq + q0) * Hh;
        #pragma unroll
        for (int r = 0; r < 8; r++) {
            int idx = tid + 128 * r;
            int q = idx >> 8, h = idx & 255;
            swq[q][h] = make_float2(qbase[q * Hh + h], Wv[h]);
        }
    }

    const float* kbase = g_kh + (long)b * KK * Hh;
    const int ktmax = (vl + 31) >> 5;

    float valbuf[16];

    for (int t = 0; t < ktmax; t++) {
        __syncthreads();   // first iter: covers swq; later: protect sk reads
        // load kh tile [32 x 256]: 2048 float4, 16/thread; scalar transposing STS
        const float4* gs = (const float4*)(kbase + (long)t * 32 * Hh);
        #pragma unroll
        for (int r = 0; r < 16; r++) {
            int i  = tid + 128 * r;
            int k  = i >> 6;
            int h0 = (i & 63) << 2;
            float4 v = gs[i];
            sk[k][h0 + 0] = v.x; sk[k][h0 + 1] = v.y;
            sk[k][h0 + 2] = v.z; sk[k][h0 + 3] = v.w;
        }
        __syncthreads();

        const float*  skrow = sk[lane];
        const float2* wq    = swq[w];
        float s0 = 0.f, s1 = 0.f;
        #pragma unroll 8
        for (int h = 0; h < Hh; h += 2) {
            float2 p0 = wq[h];
            float2 p1 = wq[h + 1];
            s0 = fmaf(p0.y, tanhx(p0.x + skrow[h]), s0);
            s1 = fmaf(p1.y, tanhx(p1.x + skrow[h + 1]), s1);
        }
        valbuf[t] = s0 + s1;
    }
    for (int t = ktmax; t < 16; t++) valbuf[t] = -1e6f;

    // masked softmax over the 512 scores held across this warp's registers
    float vals[16];
    float mx = -3.0e38f;
    #pragma unroll
    for (int i = 0; i < 16; i++) {
        float v = (i * 32 + lane < vl) ? valbuf[i] : -1e6f;
        vals[i] = v;
        mx = fmaxf(mx, v);
    }
    #pragma unroll
    for (int off = 16; off; off >>= 1)
        mx = fmaxf(mx, __shfl_xor_sync(0xffffffffu, mx, off));
    float sum = 0.f;
    #pragma unroll
    for (int i = 0; i < 16; i++) {
        float e = __expf(vals[i] - mx);   // masked -> exactly 0
        vals[i] = e;
        sum += e;
    }
    #pragma unroll
    for (int off = 16; off; off >>= 1)
        sum += __shfl_xor_sync(0xffffffffu, sum, off);
    const float inv = __fdividef(1.f, sum);
    float* dst = g_attn + (long)(b * Qq + q0 + w) * KK;
    #pragma unroll
    for (int i = 0; i < 16; i++)
        dst[i * 32 + lane] = vals[i] * inv;   // coalesced
}

// ---------------------------------------------------------------------------
// out[b] = attn[b] (64x512) @ values[b] (512x512), K bounded by valid_len
// (attn exactly 0 beyond). 64x64 tile, 4x4 microtile, double-buffered.
// grid = (Dd/64 = 8, Bb), block = 256.
// ---------------------------------------------------------------------------
__global__ __launch_bounds__(256) void av_gemm(
        const float* __restrict__ values, float* __restrict__ out,
        const int* __restrict__ vlens) {
    const int b  = blockIdx.y;
    const int bn = blockIdx.x * 64;
    const float* A  = g_attn + (long)b * Qq * KK;
    const float* Bm = values + (long)b * KK * Dd;
    float* C        = out + (long)b * Qq * Dd;
    const int nsl   = ((vlens[b] + 15) & ~15) >> 4;   // >= 1

    __shared__ float As[2][16][64];
    __shared__ float Bs[2][16][64];

    const int tid = threadIdx.x;
    const int tx  = tid & 15, ty = tid >> 4;
    const int ar0 = tid >> 2, akc = (tid & 3) << 2;
    const int br  = tid >> 4, bc  = (tid & 15) << 2;

    float4 ra, rb;
    ra = *(const float4*)(A + (long)ar0 * KK + akc);
    rb = *(const float4*)(Bm + (long)br * Dd + bn + bc);
    As[0][akc + 0][ar0] = ra.x; As[0][akc + 1][ar0] = ra.y;
    As[0][akc + 2][ar0] = ra.z; As[0][akc + 3][ar0] = ra.w;
    *(float4*)&Bs[0][br][bc] = rb;
    __syncthreads();

    float acc[4][4] = {};

    for (int s = 0; s < nsl; s++) {
        const int cur = s & 1;
        if (s + 1 < nsl) {
            const int k0 = (s + 1) * 16;
            ra = *(const float4*)(A + (long)ar0 * KK + k0 + akc);
            rb = *(const float4*)(Bm + (long)(k0 + br) * Dd + bn + bc);
        }
        #pragma unroll
        for (int kk = 0; kk < 16; kk++) {
            float4 aq = *(const float4*)&As[cur][kk][ty * 4];
            float4 bq = *(const float4*)&Bs[cur][kk][tx * 4];
            float a4[4] = {aq.x, aq.y, aq.z, aq.w};
            float b4[4] = {bq.x, bq.y, bq.z, bq.w};
            #pragma unroll
            for (int i = 0; i < 4; i++)
                #pragma unroll
                for (int j = 0; j < 4; j++)
                    acc[i][j] = fmaf(a4[i], b4[j], acc[i][j]);
        }
        if (s + 1 < nsl) {
            const int nb = (s + 1) & 1;
            As[nb][akc + 0][ar0] = ra.x; As[nb][akc + 1][ar0] = ra.y;
            As[nb][akc + 2][ar0] = ra.z; As[nb][akc + 3][ar0] = ra.w;
            *(float4*)&Bs[nb][br][bc] = rb;
        }
        __syncthreads();
    }
    #pragma unroll
    for (int i = 0; i < 4; i++) {
        float4 o = make_float4(acc[i][0], acc[i][1], acc[i][2], acc[i][3]);
        *(float4*)(C + (long)(ty * 4 + i) * Dd + bn + tx * 4) = o;
    }
}

extern "C" void kernel_launch(void* const* d_in, const int* in_sizes, int n_in,
                              void* d_out, int out_size) {
    const float* queries = (const float*)d_in[0];  // [16,64,512]
    const float* keys    = (const float*)d_in[1];  // [16,512,512]
    const float* values  = (const float*)d_in[2];  // [16,512,512]
    const int*   vlens   = (const int*)d_in[3];    // [16]
    const float* Wq      = (const float*)d_in[4];  // [512,256]
    const float* Wk      = (const float*)d_in[5];  // [512,256]
    const float* Wv      = (const float*)d_in[6];  // [256]
    float* out = (float*)d_out;                    // [16,64,512]

    proj_gemm<<<dim3(Hh / 64, (Bb * Qq + Bb * KK) / 128), 256>>>(
        queries, keys, Wq, Wk, vlens);
    score_softmax<<<Bb * (Qq / 4), 128>>>(Wv, vlens);
    av_gemm<<<dim3(Dd / 64, Bb), 256>>>(values, out, vlens);
}

// round 4
// speedup vs baseline: 2.1264x; 1.0192x over previous
#include <cuda_runtime.h>

#define Bb 16
#define Qq 64
#define KK 512
#define Dd 512
#define Hh 256

// Scratch (device globals; no allocations allowed)
__device__ float g_qh[Bb * Qq * Hh];      // 1 MB
__device__ float g_kh[Bb * KK * Hh];      // 8 MB
__device__ float g_attn[Bb * Qq * KK];    // 2 MB

__device__ __forceinline__ float tanhx(float x) {
    float y;
    asm("tanh.approx.f32 %0, %1;" : "=f"(y) : "f"(x));
    return y;
}

// ---------------------------------------------------------------------------
// Fused q-proj + k-proj GEMM. Rows [0,1024) = queries@Wq -> g_qh,
// [1024,9216) = keys@Wk -> g_kh (tiles fully past valid_len skipped).
// 128x64 tile, 128 threads, 8x8 microtile, k-slice 8, double buffered.
// grid = (4, 72), block = 128.
// ---------------------------------------------------------------------------
__global__ __launch_bounds__(128) void proj_gemm(
        const float* __restrict__ queries, const float* __restrict__ keys,
        const float* __restrict__ Wq, const float* __restrict__ Wk,
        const int* __restrict__ vlens) {
    const int row0 = blockIdx.y * 128;
    const int bn   = blockIdx.x * 64;

    const float *A, *Bm;
    float* C;
    if (row0 < Bb * Qq) {
        A = queries + (long)row0 * Dd; Bm = Wq; C = g_qh + (long)row0 * Hh;
    } else {
        const int krow = row0 - Bb * Qq;
        const int b    = krow >> 9;
        if ((krow & (KK - 1)) >= vlens[b]) return;   // fully-masked tile
        A = keys + (long)krow * Dd; Bm = Wk; C = g_kh + (long)krow * Hh;
    }

    __shared__ float As[2][8][132];   // transposed A: As[k][m], padded
    __shared__ float Bs[2][8][64];

    const int tid = threadIdx.x;
    const int tx  = tid & 7, ty = tid >> 3;           // 8 x 16 thread grid
    const int ar  = tid >> 1, ac = (tid & 1) << 2;    // A: rows ar, ar+64; k-cols ac..ac+3
    const int br  = tid >> 4, bc = (tid & 15) << 2;   // B: row br, cols bc..bc+3

    float4 ra0, ra1, rb;
    ra0 = *(const float4*)(A + (long)ar * Dd + ac);
    ra1 = *(const float4*)(A + (long)(ar + 64) * Dd + ac);
    rb  = *(const float4*)(Bm + (long)br * Hh + bn + bc);
    As[0][ac + 0][ar] = ra0.x; As[0][ac + 1][ar] = ra0.y;
    As[0][ac + 2][ar] = ra0.z; As[0][ac + 3][ar] = ra0.w;
    As[0][ac + 0][ar + 64] = ra1.x; As[0][ac + 1][ar + 64] = ra1.y;
    As[0][ac + 2][ar + 64] = ra1.z; As[0][ac + 3][ar + 64] = ra1.w;
    *(float4*)&Bs[0][br][bc] = rb;
    __syncthreads();

    float acc[8][8] = {};

    const int NS = Dd / 8;    // 64 slices
    for (int s = 0; s < NS; s++) {
        const int cur = s & 1;
        if (s + 1 < NS) {
            const int k0 = (s + 1) * 8;
            ra0 = *(const float4*)(A + (long)ar * Dd + k0 + ac);
            ra1 = *(const float4*)(A + (long)(ar + 64) * Dd + k0 + ac);
            rb  = *(const float4*)(Bm + (long)(k0 + br) * Hh + bn + bc);
        }
        #pragma unroll
        for (int kk = 0; kk < 8; kk++) {
            float4 a0 = *(const float4*)&As[cur][kk][ty * 4];
            float4 a1 = *(const float4*)&As[cur][kk][64 + ty * 4];
            float4 b0 = *(const float4*)&Bs[cur][kk][tx * 4];
            float4 b1 = *(const float4*)&Bs[cur][kk][32 + tx * 4];
            float am[8] = {a0.x, a0.y, a0.z, a0.w, a1.x, a1.y, a1.z, a1.w};
            float bn8[8] = {b0.x, b0.y, b0.z, b0.w, b1.x, b1.y, b1.z, b1.w};
            #pragma unroll
            for (int i = 0; i < 8; i++)
                #pragma unroll
                for (int j = 0; j < 8; j++)
                    acc[i][j] = fmaf(am[i], bn8[j], acc[i][j]);
        }
        if (s + 1 < NS) {
            const int nb = (s + 1) & 1;
            As[nb][ac + 0][ar] = ra0.x; As[nb][ac + 1][ar] = ra0.y;
            As[nb][ac + 2][ar] = ra0.z; As[nb][ac + 3][ar] = ra0.w;
            As[nb][ac + 0][ar + 64] = ra1.x; As[nb][ac + 1][ar + 64] = ra1.y;
            As[nb][ac + 2][ar + 64] = ra1.z; As[nb][ac + 3][ar + 64] = ra1.w;
            *(float4*)&Bs[nb][br][bc] = rb;
        }
        __syncthreads();
    }

    #pragma unroll
    for (int i = 0; i < 8; i++) {
        const int row = (i < 4) ? (ty * 4 + i) : (64 + ty * 4 + i - 4);
        float4 o0 = make_float4(acc[i][0], acc[i][1], acc[i][2], acc[i][3]);
        float4 o1 = make_float4(acc[i][4], acc[i][5], acc[i][6], acc[i][7]);
        *(float4*)(C + (long)row * Hh + bn + tx * 4)      = o0;
        *(float4*)(C + (long)row * Hh + bn + 32 + tx * 4) = o1;
    }
}

// ---------------------------------------------------------------------------
// Fused scoring + masked softmax. 256 threads = 8 warps.
// Warp w -> q-row (q0 + (w&3)), k-half (w>>2). Stage = 64 k-rows in sk.
// Lane = k within 32-run: zero shuffles in scoring; warp-pair softmax combine.
// Dynamic smem: swq[4][256] float2 (qh,Wv) + sk[64][257] floats.
// grid = Bb*(Qq/4) = 256, block = 256.
// ---------------------------------------------------------------------------
#define SCORE_SMEM (4 * 256 * 8 + 64 * 257 * 4)

__global__ __launch_bounds__(256) void score_softmax(
        const float* __restrict__ Wv, const int* __restrict__ vlens) {
    extern __shared__ char smem_raw[];
    float2* swq = (float2*)smem_raw;                       // [4][256]
    float*  sk  = (float*)(smem_raw + 4 * 256 * 8);        // [64][257]
    __shared__ float smax[8], ssum[8];

    const int bq   = blockIdx.x;
    const int b    = bq >> 4;
    const int q0   = (bq & 15) * 4;
    const int tid  = threadIdx.x;
    const int lane = tid & 31;
    const int w    = tid >> 5;
    const int q    = w & 3;
    const int kh   = w >> 2;
    const int vl   = vlens[b];

    // fill swq (1024 float2, 4 per thread)
    {
        const float* qbase = g_qh + (long)(b * Qq + q0) * Hh;
        #pragma unroll
        for (int r = 0; r < 4; r++) {
            int idx = tid + 256 * r;
            swq[idx] = make_float2(qbase[idx], Wv[idx & 255]);
        }
    }

    const float* kbase = g_kh + (long)b * KK * Hh;
    const int nst = (vl + 63) >> 6;       // 64-row stages

    float valbuf[8];

    for (int s = 0; s < nst; s++) {
        __syncthreads();   // first iter covers swq; later protects sk reads
        // load 64x256 kh tile: 4096 float4, 16/thread, coalesced
        const float4* gs = (const float4*)(kbase + (long)s * 64 * Hh);
        #pragma unroll
        for (int r = 0; r < 16; r++) {
            int i  = tid + 256 * r;
            int k  = i >> 6;
            int h0 = (i & 63) << 2;
            float4 v = gs[i];
            float* p = sk + k * 257 + h0;
            p[0] = v.x; p[1] = v.y; p[2] = v.z; p[3] = v.w;
        }
        __syncthreads();

        float sv = -1e6f;
        if ((2 * s + kh) * 32 < vl) {
            const float*  skrow = sk + (kh * 32 + lane) * 257;
            const float4* wq4   = (const float4*)(swq + q * 256);
            float s0 = 0.f, s1 = 0.f;
            #pragma unroll 8
            for (int hh = 0; hh < Hh / 2; hh++) {
                float4 p = wq4[hh];         // (qh[2hh], Wv[2hh], qh[2hh+1], Wv[2hh+1])
                s0 = fmaf(p.y, tanhx(p.x + skrow[2 * hh]), s0);
                s1 = fmaf(p.w, tanhx(p.z + skrow[2 * hh + 1]), s1);
            }
            sv = s0 + s1;
        }
        valbuf[s] = sv;
    }
    #pragma unroll
    for (int s2 = 0; s2 < 8; s2++) if (s2 >= nst) valbuf[s2] = -1e6f;

    // masked softmax: this warp holds k = 64*i + 32*kh + lane, i < 8
    float vals[8];
    float mx = -3.0e38f;
    #pragma unroll
    for (int i = 0; i < 8; i++) {
        int k = 64 * i + 32 * kh + lane;
        float v = (k < vl) ? valbuf[i] : -1e6f;
        vals[i] = v;
        mx = fmaxf(mx, v);
    }
    #pragma unroll
    for (int off = 16; off; off >>= 1)
        mx = fmaxf(mx, __shfl_xor_sync(0xffffffffu, mx, off));
    if (lane == 0) smax[w] = mx;
    __syncthreads();
    const float gmx = fmaxf(smax[w], smax[w ^ 4]);

    float sum = 0.f;
    #pragma unroll
    for (int i = 0; i < 8; i++) {
        float e = __expf(vals[i] - gmx);   // masked -> exactly 0
        vals[i] = e;
        sum += e;
    }
    #pragma unroll
    for (int off = 16; off; off >>= 1)
        sum += __shfl_xor_sync(0xffffffffu, sum, off);
    if (lane == 0) ssum[w] = sum;
    __syncthreads();
    const float inv = __fdividef(1.f, ssum[w] + ssum[w ^ 4]);

    float* dst = g_attn + (long)(b * Qq + q0 + q) * KK;
    for (int i = 0; i < nst; i++)          // av_gemm reads only k < align16(vl) <= 64*nst
        dst[64 * i + 32 * kh + lane] = vals[i] * inv;
}

// ---------------------------------------------------------------------------
// out[b] = attn[b] (64x512) @ values[b] (512x512), K bounded by valid_len
// (attn exactly 0 beyond). 64x64 tile, 4x4 microtile, double-buffered.
// grid = (8, 16), block = 256.
// ---------------------------------------------------------------------------
__global__ __launch_bounds__(256) void av_gemm(
        const float* __restrict__ values, float* __restrict__ out,
        const int* __restrict__ vlens) {
    const int b  = blockIdx.y;
    const int bn = blockIdx.x * 64;
    const float* A  = g_attn + (long)b * Qq * KK;
    const float* Bm = values + (long)b * KK * Dd;
    float* C        = out + (long)b * Qq * Dd;
    const int nsl   = ((vlens[b] + 15) & ~15) >> 4;   // >= 1

    __shared__ float As[2][16][64];
    __shared__ float Bs[2][16][64];

    const int tid = threadIdx.x;
    const int tx  = tid & 15, ty = tid >> 4;
    const int ar0 = tid >> 2, akc = (tid & 3) << 2;
    const int br  = tid >> 4, bc  = (tid & 15) << 2;

    float4 ra, rb;
    ra = *(const float4*)(A + (long)ar0 * KK + akc);
    rb = *(const float4*)(Bm + (long)br * Dd + bn + bc);
    As[0][akc + 0][ar0] = ra.x; As[0][akc + 1][ar0] = ra.y;
    As[0][akc + 2][ar0] = ra.z; As[0][akc + 3][ar0] = ra.w;
    *(float4*)&Bs[0][br][bc] = rb;
    __syncthreads();

    float acc[4][4] = {};

    for (int s = 0; s < nsl; s++) {
        const int cur = s & 1;
        if (s + 1 < nsl) {
            const int k0 = (s + 1) * 16;
            ra = *(const float4*)(A + (long)ar0 * KK + k0 + akc);
            rb = *(const float4*)(Bm + (long)(k0 + br) * Dd + bn + bc);
        }
        #pragma unroll
        for (int kk = 0; kk < 16; kk++) {
            float4 aq = *(const float4*)&As[cur][kk][ty * 4];
            float4 bq = *(const float4*)&Bs[cur][kk][tx * 4];
            float a4[4] = {aq.x, aq.y, aq.z, aq.w};
            float b4[4] = {bq.x, bq.y, bq.z, bq.w};
            #pragma unroll
            for (int i = 0; i < 4; i++)
                #pragma unroll
                for (int j = 0; j < 4; j++)
                    acc[i][j] = fmaf(a4[i], b4[j], acc[i][j]);
        }
        if (s + 1 < nsl) {
            const int nb = (s + 1) & 1;
            As[nb][akc + 0][ar0] = ra.x; As[nb][akc + 1][ar0] = ra.y;
            As[nb][akc + 2][ar0] = ra.z; As[nb][akc + 3][ar0] = ra.w;
            *(float4*)&Bs[nb][br][bc] = rb;
        }
        __syncthreads();
    }
    #pragma unroll
    for (int i = 0; i < 4; i++) {
        float4 o = make_float4(acc[i][0], acc[i][1], acc[i][2], acc[i][3]);
        *(float4*)(C + (long)(ty * 4 + i) * Dd + bn + tx * 4) = o;
    }
}

extern "C" void kernel_launch(void* const* d_in, const int* in_sizes, int n_in,
                              void* d_out, int out_size) {
    const float* queries = (const float*)d_in[0];  // [16,64,512]
    const float* keys    = (const float*)d_in[1];  // [16,512,512]
    const float* values  = (const float*)d_in[2];  // [16,512,512]
    const int*   vlens   = (const int*)d_in[3];    // [16]
    const float* Wq      = (const float*)d_in[4];  // [512,256]
    const float* Wk      = (const float*)d_in[5];  // [512,256]
    const float* Wv      = (const float*)d_in[6];  // [256]
    float* out = (float*)d_out;                    // [16,64,512]

    cudaFuncSetAttribute(score_softmax,
                         cudaFuncAttributeMaxDynamicSharedMemorySize, SCORE_SMEM);

    proj_gemm<<<dim3(Hh / 64, (Bb * Qq + Bb * KK) / 128), 128>>>(
        queries, keys, Wq, Wk, vlens);
    score_softmax<<<Bb * (Qq / 4), 256, SCORE_SMEM>>>(Wv, vlens);
    av_gemm<<<dim3(Dd / 64, Bb), 256>>>(values, out, vlens);
}